// round 1
// baseline (speedup 1.0000x reference)
#include <cuda_runtime.h>
#include <cstdint>

// Problem geometry: frames (4,8,2,4,480,640) fp32 -> dense (32, 8, 480, 640)
#define BF_TOTAL   32u          // B*S = 4*8
#define CH         8u           // N_evt*C_evt = 2*4
#define HW         307200u      // 480*640
#define WIDTH      640u
#define TOTAL_PIX  9830400u     // 32*307200
#define TILE       4096u        // pixels per tile (307200 = 75*4096 -> tile within one bf)
#define NTILES     2400u
#define THREADS    256
#define MAXPTS     200000u
#define FEAT_OFF   0u
#define COORD_OFF  1600000u     // 200000*8
#define THRESH     3.0f

// Decoupled-lookback state: bits[31:30] = {0:invalid,1:aggregate,2:prefix}, bits[29:0] = value
__device__ unsigned int g_status[NTILES];
__device__ unsigned int g_tile_counter;

__device__ __forceinline__ float4 fabs4(float4 v) {
    return make_float4(fabsf(v.x), fabsf(v.y), fabsf(v.z), fabsf(v.w));
}
__device__ __forceinline__ float4 max4(float4 a, float4 b) {
    return make_float4(fmaxf(a.x, b.x), fmaxf(a.y, b.y), fmaxf(a.z, b.z), fmaxf(a.w, b.w));
}

// ---------------------------------------------------------------------------
// Init kernel: zero output buffer, reset lookback status + tile counter.
// ---------------------------------------------------------------------------
__global__ void init_kernel(float* __restrict__ out, unsigned out_n) {
    unsigned idx = blockIdx.x * blockDim.x + threadIdx.x;
    unsigned stride = gridDim.x * blockDim.x;
    for (unsigned i = idx; i < out_n; i += stride) out[i] = 0.0f;
    for (unsigned i = idx; i < NTILES; i += stride) g_status[i] = 0u;
    if (idx == 0) g_tile_counter = 0u;
}

// ---------------------------------------------------------------------------
// Main kernel: single-pass ordered compaction with decoupled lookback.
// ---------------------------------------------------------------------------
__global__ __launch_bounds__(THREADS) void voxelizer_kernel(
    const float* __restrict__ in, float* __restrict__ out)
{
    __shared__ unsigned s_hits[TILE];   // pixel index within bf slice, compacted in order
    __shared__ int      s_warp[8];
    __shared__ unsigned s_tile;
    __shared__ unsigned s_excl;

    const int tid  = threadIdx.x;
    const int lane = tid & 31;
    const int wid  = tid >> 5;

    if (tid == 0) s_tile = atomicAdd(&g_tile_counter, 1u);
    __syncthreads();
    const unsigned tile = s_tile;

    const unsigned bf = tile / 75u;               // tile fully within one bf slice
    const unsigned p_base = (tile % 75u) * TILE;  // pixel offset within the bf slice
    const float4* __restrict__ slice4 =
        reinterpret_cast<const float4*>(in + (size_t)bf * (CH * HW));

    int running = 0;  // tile-local hit count so far (identical on all threads)

    #pragma unroll
    for (int it = 0; it < 4; ++it) {
        // This thread covers 4 consecutive pixels (never crosses a row: 640%4==0)
        const unsigned p0 = p_base + (unsigned)it * 1024u + (unsigned)tid * 4u;
        const float4* b4 = slice4 + (p0 >> 2);

        float4 mx = fabs4(b4[0]);
        #pragma unroll
        for (int c = 1; c < 8; ++c)
            mx = max4(mx, fabs4(b4[(size_t)c * (HW / 4u)]));

        unsigned hm = (mx.x > THRESH ? 1u : 0u) |
                      (mx.y > THRESH ? 2u : 0u) |
                      (mx.z > THRESH ? 4u : 0u) |
                      (mx.w > THRESH ? 8u : 0u);
        int cnt = __popc(hm);

        // warp inclusive scan of per-thread counts
        int incl = cnt;
        #pragma unroll
        for (int o = 1; o < 32; o <<= 1) {
            int n = __shfl_up_sync(0xffffffffu, incl, o);
            if (lane >= o) incl += n;
        }
        if (lane == 31) s_warp[wid] = incl;   // warp total
        __syncthreads();

        int wexcl = 0, ittotal = 0;
        #pragma unroll
        for (int w = 0; w < 8; ++w) {
            int c = s_warp[w];
            if (w < wid) wexcl += c;
            ittotal += c;
        }

        int idx = running + wexcl + (incl - cnt);
        #pragma unroll
        for (int j = 0; j < 4; ++j) {
            if ((hm >> j) & 1u) s_hits[idx++] = p0 + (unsigned)j;
        }
        running += ittotal;
        __syncthreads();   // protect s_warp for next iter; also orders s_hits
    }

    const unsigned tile_total = (unsigned)running;

    // Publish aggregate (or inclusive prefix for tile 0)
    if (tid == 0) {
        unsigned word = ((tile == 0u) ? (2u << 30) : (1u << 30)) | tile_total;
        __threadfence();
        atomicExch(&g_status[tile], word);
        if (tile == 0u) s_excl = 0u;
    }

    // Warp-parallel decoupled lookback (warp 0)
    if (wid == 0 && tile > 0u) {
        unsigned excl = 0u;
        int wbase = (int)tile;
        while (true) {
            int idx = wbase - 32 + lane;
            unsigned s;
            do {
                s = (idx >= 0) ? *(volatile unsigned*)&g_status[idx]
                               : (2u << 30);     // virtual prefix=0 before tile 0
            } while (__any_sync(0xffffffffu, (s >> 30) == 0u));

            unsigned pmask = __ballot_sync(0xffffffffu, (s >> 30) == 2u);
            unsigned contrib;
            int done;
            if (pmask) {
                int h = 31 - __clz(pmask);       // highest lane holding a prefix
                contrib = (lane >= h) ? (s & 0x3fffffffu) : 0u;
                done = 1;
            } else {
                contrib = s & 0x3fffffffu;
                done = 0;
            }
            #pragma unroll
            for (int o = 16; o; o >>= 1)
                contrib += __shfl_down_sync(0xffffffffu, contrib, o);
            contrib = __shfl_sync(0xffffffffu, contrib, 0);
            excl += contrib;
            if (done) break;
            wbase -= 32;
        }
        if (lane == 0) {
            s_excl = excl;
            __threadfence();
            atomicExch(&g_status[tile], (2u << 30) | (excl + tile_total));
        }
    }
    __syncthreads();
    const unsigned excl = s_excl;

    if (excl >= MAXPTS) return;   // nothing from this tile fits

    // Scatter: ranks [excl, excl + tile_total) -> output, capped at MAXPTS.
    // Feature re-reads hit L1/L2 (same block just streamed this tile).
    for (unsigned j = tid; j < tile_total; j += THREADS) {
        unsigned rank = excl + j;
        if (rank >= MAXPTS) break;
        unsigned p = s_hits[j];
        const float* src = in + (size_t)bf * (CH * HW) + p;
        float* f = out + FEAT_OFF + (size_t)rank * 8u;
        #pragma unroll
        for (int c = 0; c < 8; ++c)
            f[c] = __ldg(src + (size_t)c * HW);
        float* cd = out + COORD_OFF + (size_t)rank * 4u;
        cd[0] = (float)(bf >> 3);      // batch = bf / S (S=8)
        cd[1] = (float)(bf & 7u);      // time  = bf % S
        cd[2] = (float)(p / WIDTH);    // y
        cd[3] = (float)(p % WIDTH);    // x
    }
}

// ---------------------------------------------------------------------------
extern "C" void kernel_launch(void* const* d_in, const int* in_sizes, int n_in,
                              void* d_out, int out_size)
{
    const float* frames = (const float*)d_in[0];
    float* out = (float*)d_out;

    init_kernel<<<512, 256>>>(out, (unsigned)out_size);
    voxelizer_kernel<<<NTILES, THREADS>>>(frames, out);
}